// round 1
// baseline (speedup 1.0000x reference)
#include <cuda_runtime.h>

#define NN 50000
#define EE 800000
#define CC 64
#define MCC 128

typedef unsigned long long ull;

// ---------------- device scratch (static allocation is the allowed path) ----------------
__device__ __align__(16) float g_feat[NN * CC];    // layernormed features
__device__ __align__(16) float g_agg[NN * MCC];    // message accumulation
__device__ __align__(16) float g_deg[NN];
__device__ __align__(16) float g_gsum[CC];         // column sums of feat
__device__ __align__(16) float g_gctx[CC];         // global context vector
__device__ __align__(16) float g_misc[4];          // u0,u1,u2, tanh(res_scale)

// ---------------- f32x2 packed math ----------------
__device__ __forceinline__ ull pack2(float lo, float hi) {
    ull r; asm("mov.b64 %0, {%1, %2};" : "=l"(r) : "f"(lo), "f"(hi)); return r;
}
__device__ __forceinline__ void fma2(ull& d, ull a, ull b) {
    asm("fma.rn.f32x2 %0, %1, %2, %0;" : "+l"(d) : "l"(a), "l"(b));
}
__device__ __forceinline__ float2 unpack2(ull v) {
    float2 f; asm("mov.b64 {%0, %1}, %2;" : "=f"(f.x), "=f"(f.y) : "l"(v)); return f;
}
__device__ __forceinline__ float gelu_exact(float x) {
    return 0.5f * x * (1.0f + erff(x * 0.7071067811865476f));
}

// ---------------- zero scratch ----------------
__global__ void k_zero() {
    int i = blockIdx.x * blockDim.x + threadIdx.x;
    int stride = gridDim.x * blockDim.x;
    float4 z = make_float4(0.f, 0.f, 0.f, 0.f);
    for (int j = i; j < NN * MCC / 4; j += stride) ((float4*)g_agg)[j] = z;
    for (int j = i; j < NN; j += stride) g_deg[j] = 0.f;
    if (i < CC) g_gsum[i] = 0.f;
}

// ---------------- layernorm + global column-sum partials ----------------
__global__ void k_lnorm(const float* __restrict__ h,
                        const float* __restrict__ lng,
                        const float* __restrict__ lnb) {
    __shared__ float cs[CC];
    int tid = threadIdx.x, lane = tid & 31, w = tid >> 5;
    int n = blockIdx.x * 4 + w;
    float2 v = ((const float2*)h)[n * 32 + lane];
    float s = v.x + v.y, q = v.x * v.x + v.y * v.y;
#pragma unroll
    for (int o = 16; o; o >>= 1) {
        s += __shfl_xor_sync(~0u, s, o);
        q += __shfl_xor_sync(~0u, q, o);
    }
    float mu = s * (1.f / 64.f);
    float var = q * (1.f / 64.f) - mu * mu;
    float rstd = rsqrtf(var + 1e-5f);
    float f0 = (v.x - mu) * rstd * lng[2 * lane] + lnb[2 * lane];
    float f1 = (v.y - mu) * rstd * lng[2 * lane + 1] + lnb[2 * lane + 1];
    ((float2*)g_feat)[n * 32 + lane] = make_float2(f0, f1);
    if (tid < CC) cs[tid] = 0.f;
    __syncthreads();
    atomicAdd(&cs[2 * lane], f0);
    atomicAdd(&cs[2 * lane + 1], f1);
    __syncthreads();
    if (tid < CC) atomicAdd(&g_gsum[tid], cs[tid]);
}

// ---------------- tiny global MLP + misc scalars ----------------
__global__ void k_global(const float* __restrict__ fdir,
                         const float* glw1, const float* glb1,
                         const float* glw2, const float* glb2,
                         const float* glw3, const float* glb3,
                         const float* res_scale) {
    __shared__ float a0[CC], a1[CC], a2[CC];
    int t = threadIdx.x;
    if (t < CC) a0[t] = g_gsum[t] * (1.f / (float)NN);
    __syncthreads();
    if (t < CC) {
        float acc = glb1[t];
        for (int k = 0; k < CC; k++) acc += a0[k] * glw1[k * CC + t];
        a1[t] = gelu_exact(acc);
    }
    __syncthreads();
    if (t < CC) {
        float acc = glb2[t];
        for (int k = 0; k < CC; k++) acc += a1[k] * glw2[k * CC + t];
        a2[t] = gelu_exact(acc);
    }
    __syncthreads();
    if (t < CC) {
        float acc = glb3[t];
        for (int k = 0; k < CC; k++) acc += a2[k] * glw3[k * CC + t];
        g_gctx[t] = acc;
    }
    if (t == 0) {
        float u0 = fdir[0], u1 = fdir[1], u2 = fdir[2];
        float inv = 1.f / (sqrtf(u0 * u0 + u1 * u1 + u2 * u2) + 1e-8f);
        g_misc[0] = u0 * inv; g_misc[1] = u1 * inv; g_misc[2] = u2 * inv;
        g_misc[3] = tanhf(res_scale[0]);
    }
}

// ---------------- tiled GEMM: [64 x K](smem) @ [K x NOUT](gmem, staged) -> [64 x NOUT](smem)
// 256 threads, each computes a 4x(NOUT/16) micro-tile via packed f32x2 FMA.
template <int NOUT, bool DOGELU>
__device__ __forceinline__ void tile_gemm(const float* __restrict__ A, int sA, int K,
                                          const float* __restrict__ W,
                                          const float* __restrict__ bias,
                                          float* __restrict__ Ws,
                                          float* __restrict__ Out, int sO, int tid) {
    constexpr int CPT = NOUT / 16;   // cols per thread (8 or 4)
    constexpr int PAIRS = CPT / 2;   // f32x2 accumulators per row (4 or 2)
    const int tx = tid & 15, ty = tid >> 4;
    ull acc[4][PAIRS];
#pragma unroll
    for (int r = 0; r < 4; r++)
#pragma unroll
        for (int p = 0; p < PAIRS; p++) acc[r][p] = 0ULL;

    const float* Ar0 = A + (ty * 4) * sA;

    for (int k0 = 0; k0 < K; k0 += 32) {
        int kc = K - k0; if (kc > 32) kc = 32;
        __syncthreads();
        {
            const float4* src = (const float4*)(W + k0 * NOUT);
            float4* dst = (float4*)Ws;
            int tot = kc * (NOUT / 4);
            for (int i = tid; i < tot; i += 256) dst[i] = src[i];
        }
        __syncthreads();
        if (kc == 32) {
#pragma unroll
            for (int kq = 0; kq < 8; kq++) {
                float4 av[4];
#pragma unroll
                for (int r = 0; r < 4; r++)
                    av[r] = *(const float4*)(Ar0 + r * sA + k0 + kq * 4);
#pragma unroll
                for (int j = 0; j < 4; j++) {
                    const float* wr = Ws + (kq * 4 + j) * NOUT + tx * CPT;
                    ull bp[PAIRS];
#pragma unroll
                    for (int p = 0; p < PAIRS; p++)
                        bp[p] = *(const ull*)(wr + 2 * p);
#pragma unroll
                    for (int r = 0; r < 4; r++) {
                        float a = ((const float*)&av[r])[j];
                        ull aa = pack2(a, a);
#pragma unroll
                        for (int p = 0; p < PAIRS; p++) fma2(acc[r][p], aa, bp[p]);
                    }
                }
            }
        } else {
            for (int kk = 0; kk < kc; kk++) {
                const float* wr = Ws + kk * NOUT + tx * CPT;
                ull bp[PAIRS];
#pragma unroll
                for (int p = 0; p < PAIRS; p++)
                    bp[p] = *(const ull*)(wr + 2 * p);
#pragma unroll
                for (int r = 0; r < 4; r++) {
                    float a = Ar0[r * sA + k0 + kk];
                    ull aa = pack2(a, a);
#pragma unroll
                    for (int p = 0; p < PAIRS; p++) fma2(acc[r][p], aa, bp[p]);
                }
            }
        }
    }
    // epilogue
    const float* brow = bias + tx * CPT;
#pragma unroll
    for (int r = 0; r < 4; r++) {
        float* orow = Out + (ty * 4 + r) * sO + tx * CPT;
#pragma unroll
        for (int p = 0; p < PAIRS; p++) {
            float2 v = unpack2(acc[r][p]);
            float x0 = v.x + brow[2 * p];
            float x1 = v.y + brow[2 * p + 1];
            if (DOGELU) { x0 = gelu_exact(x0); x1 = gelu_exact(x1); }
            orow[2 * p] = x0;
            orow[2 * p + 1] = x1;
        }
    }
}

// ---------------- edge kernel: gather -> edge MLP -> gate -> atomic scatter ----------------
// dyn smem floats: Xs[64*200) | B1[64*132) | Ws[32*128) | gate[64) | uu[4) | rs[64] cs[64]
#define SME_XS 0
#define SME_B1 12800
#define SME_WS 21248
#define SME_GATE 25344
#define SME_UU 25408
#define SME_IDX 25412
#define SME_EDGE_FLOATS 25540

__global__ void __launch_bounds__(256, 2) k_edge(
    const int* __restrict__ ei, const float* __restrict__ coords,
    const float* ew1, const float* eb1, const float* ew2, const float* eb2,
    const float* ew3, const float* eb3, const float* gw1, const float* gb1,
    const float* gw2, const float* gb2) {
    extern __shared__ float sm[];
    float* Xs = sm + SME_XS;
    float* B1 = sm + SME_B1;
    float* Ws = sm + SME_WS;
    float* gate = sm + SME_GATE;
    float* uu = sm + SME_UU;
    int* rs = (int*)(sm + SME_IDX);
    int* cs2 = rs + 64;
    int tid = threadIdx.x;
    int e0 = blockIdx.x * 64;

    if (tid < 64) { rs[tid] = ei[e0 + tid]; cs2[tid] = ei[EE + e0 + tid]; }
    if (tid < 4) uu[tid] = g_misc[tid];
    __syncthreads();

    for (int idx = tid; idx < 64 * 64; idx += 256) {
        int e = idx >> 6, c = idx & 63;
        float fi = g_feat[rs[e] * 64 + c];
        float fj = g_feat[cs2[e] * 64 + c];
        float* xr = Xs + e * 200;
        xr[c] = fi; xr[64 + c] = fj; xr[128 + c] = fi - fj;
    }
    if (tid < 64) {
        int e = tid, r = rs[e], c = cs2[e];
        float xi0 = coords[r * 3], xi1 = coords[r * 3 + 1], xi2 = coords[r * 3 + 2];
        float xj0 = coords[c * 3], xj1 = coords[c * 3 + 1], xj2 = coords[c * 3 + 2];
        float r0 = xi0 - xj0, r1 = xi1 - xj1, r2 = xi2 - xj2;
        float u0 = uu[0], u1 = uu[1], u2 = uu[2];
        float* xr = Xs + e * 200;
        xr[192] = r0 * r0 + r1 * r1 + r2 * r2;
        xr[193] = xi0 * u0 + xi1 * u1 + xi2 * u2;
        xr[194] = xj0 * u0 + xj1 * u1 + xj2 * u2;
        xr[195] = r0 * u0 + r1 * u1 + r2 * u2;
    }
    __syncthreads();

    tile_gemm<128, true >(Xs, 200, 196, ew1, eb1, Ws, B1, 132, tid);  // h1
    tile_gemm<128, true >(B1, 132, 128, ew2, eb2, Ws, Xs, 132, tid);  // h2
    tile_gemm<128, false>(Xs, 132, 128, ew3, eb3, Ws, B1, 132, tid);  // edge_hidden
    tile_gemm<128, true >(B1, 132, 128, gw1, gb1, Ws, Xs, 132, tid);  // gate hidden
    __syncthreads();

    if (tid < 64) {
        float acc = gb2[0];
        const float* gr = Xs + tid * 132;
#pragma unroll 8
        for (int k = 0; k < 128; k++) acc += gr[k] * gw2[k];
        gate[tid] = 1.f / (1.f + expf(-acc));
    }
    __syncthreads();

    for (int idx = tid; idx < 64 * 128; idx += 256) {
        int e = idx >> 7, c2 = idx & 127;
        float v = gate[e] * B1[e * 132 + c2];
        atomicAdd(&g_agg[rs[e] * 128 + c2], v);
    }
    if (tid < 64) atomicAdd(&g_deg[rs[tid]], 1.f);
}

// ---------------- node update kernel ----------------
// dyn smem floats: Un[64*260) | B1[64*132) | Ws[32*128) | dg[64)
#define SMU_UN 0
#define SMU_B1 16640
#define SMU_WS 25088
#define SMU_DG 29184
#define SMU_UPD_FLOATS 29248

__global__ void __launch_bounds__(256, 1) k_update(
    const float* uw1, const float* ub1, const float* uw2, const float* ub2,
    const float* uw3, const float* ub3, float* __restrict__ out) {
    extern __shared__ float sm[];
    float* Un = sm + SMU_UN;
    float* B1 = sm + SMU_B1;
    float* Ws = sm + SMU_WS;
    float* dg = sm + SMU_DG;
    int tid = threadIdx.x;
    int n0 = blockIdx.x * 64;

    if (tid < 64) {
        int n = n0 + tid; if (n >= NN) n = NN - 1;
        float d = g_deg[n]; if (d < 1.f) d = 1.f;
        dg[tid] = 1.f / d;
    }
    __syncthreads();
    for (int idx = tid; idx < 64 * 64; idx += 256) {
        int e = idx >> 6, c = idx & 63;
        int n = n0 + e; if (n >= NN) n = NN - 1;
        Un[e * 260 + c] = g_feat[n * 64 + c];
        Un[e * 260 + 192 + c] = g_gctx[c];
    }
    for (int idx = tid; idx < 64 * 128; idx += 256) {
        int e = idx >> 7, c = idx & 127;
        int n = n0 + e; if (n >= NN) n = NN - 1;
        Un[e * 260 + 64 + c] = g_agg[n * 128 + c] * dg[e];
    }
    __syncthreads();

    tile_gemm<128, true >(Un, 260, 256, uw1, ub1, Ws, B1, 132, tid);
    tile_gemm<128, true >(B1, 132, 128, uw2, ub2, Ws, Un, 132, tid);
    tile_gemm<64, false>(Un, 132, 128, uw3, ub3, Ws, B1, 132, tid);
    __syncthreads();

    float ts = g_misc[3];
    for (int idx = tid; idx < 64 * 64; idx += 256) {
        int e = idx >> 6, c = idx & 63;
        int n = n0 + e;
        if (n < NN) out[n * 64 + c] = ts * B1[e * 132 + c];
    }
}

// ---------------- launch ----------------
extern "C" void kernel_launch(void* const* d_in, const int* in_sizes, int n_in,
                              void* d_out, int out_size) {
    const float* coords   = (const float*)d_in[0];
    const float* h        = (const float*)d_in[1];
    const float* fdir     = (const float*)d_in[2];
    const int*   ei       = (const int*)d_in[3];
    const float* ln_g     = (const float*)d_in[4];
    const float* ln_b     = (const float*)d_in[5];
    const float* ew1      = (const float*)d_in[6];
    const float* eb1      = (const float*)d_in[7];
    const float* ew2      = (const float*)d_in[8];
    const float* eb2      = (const float*)d_in[9];
    const float* ew3      = (const float*)d_in[10];
    const float* eb3      = (const float*)d_in[11];
    const float* gw1      = (const float*)d_in[12];
    const float* gb1      = (const float*)d_in[13];
    const float* gw2      = (const float*)d_in[14];
    const float* gb2      = (const float*)d_in[15];
    const float* glw1     = (const float*)d_in[16];
    const float* glb1     = (const float*)d_in[17];
    const float* glw2     = (const float*)d_in[18];
    const float* glb2     = (const float*)d_in[19];
    const float* glw3     = (const float*)d_in[20];
    const float* glb3     = (const float*)d_in[21];
    const float* uw1      = (const float*)d_in[22];
    const float* ub1      = (const float*)d_in[23];
    const float* uw2      = (const float*)d_in[24];
    const float* ub2      = (const float*)d_in[25];
    const float* uw3      = (const float*)d_in[26];
    const float* ub3      = (const float*)d_in[27];
    const float* rscale   = (const float*)d_in[28];
    float* out = (float*)d_out;

    cudaFuncSetAttribute(k_edge, cudaFuncAttributeMaxDynamicSharedMemorySize,
                         SME_EDGE_FLOATS * 4);
    cudaFuncSetAttribute(k_update, cudaFuncAttributeMaxDynamicSharedMemorySize,
                         SMU_UPD_FLOATS * 4);

    k_zero<<<2048, 256>>>();
    k_lnorm<<<NN / 4, 128>>>(h, ln_g, ln_b);
    k_global<<<1, 64>>>(fdir, glw1, glb1, glw2, glb2, glw3, glb3, rscale);
    k_edge<<<EE / 64, 256, SME_EDGE_FLOATS * 4>>>(ei, coords,
        ew1, eb1, ew2, eb2, ew3, eb3, gw1, gb1, gw2, gb2);
    k_update<<<(NN + 63) / 64, 256, SMU_UPD_FLOATS * 4>>>(
        uw1, ub1, uw2, ub2, uw3, ub3, out);
}

// round 2
// speedup vs baseline: 1.4606x; 1.4606x over previous
#include <cuda_runtime.h>

#define NN 50000
#define EE 800000
#define CC 64
#define MCC 128

typedef unsigned long long ull;

// ---------------- device scratch ----------------
__device__ __align__(16) float g_feat[NN * CC];    // layernormed features
__device__ __align__(16) float g_agg[NN * MCC];    // message accumulation
__device__ __align__(16) float g_deg[NN];
__device__ __align__(16) float g_gsum[CC];         // column sums of feat
__device__ __align__(16) float g_gctx[CC];         // global context vector
__device__ __align__(16) float g_misc[4];          // u0,u1,u2, tanh(res_scale)

// ---------------- f32x2 packed math ----------------
__device__ __forceinline__ ull pack2(float lo, float hi) {
    ull r; asm("mov.b64 %0, {%1, %2};" : "=l"(r) : "f"(lo), "f"(hi)); return r;
}
__device__ __forceinline__ void fma2(ull& d, ull a, ull b) {
    asm("fma.rn.f32x2 %0, %1, %2, %0;" : "+l"(d) : "l"(a), "l"(b));
}
__device__ __forceinline__ float2 unpack2(ull v) {
    float2 f; asm("mov.b64 {%0, %1}, %2;" : "=f"(f.x), "=f"(f.y) : "l"(v)); return f;
}
__device__ __forceinline__ float gelu_exact(float x) {
    return 0.5f * x * (1.0f + erff(x * 0.7071067811865476f));
}

// ---------------- zero scratch ----------------
__global__ void k_zero() {
    int i = blockIdx.x * blockDim.x + threadIdx.x;
    int stride = gridDim.x * blockDim.x;
    float4 z = make_float4(0.f, 0.f, 0.f, 0.f);
    for (int j = i; j < NN * MCC / 4; j += stride) ((float4*)g_agg)[j] = z;
    for (int j = i; j < NN; j += stride) g_deg[j] = 0.f;
    if (i < CC) g_gsum[i] = 0.f;
}

// ---------------- layernorm + global column-sum partials ----------------
__global__ void k_lnorm(const float* __restrict__ h,
                        const float* __restrict__ lng,
                        const float* __restrict__ lnb) {
    __shared__ float cs[CC];
    int tid = threadIdx.x, lane = tid & 31, w = tid >> 5;
    int n = blockIdx.x * 4 + w;
    float2 v = ((const float2*)h)[n * 32 + lane];
    float s = v.x + v.y, q = v.x * v.x + v.y * v.y;
#pragma unroll
    for (int o = 16; o; o >>= 1) {
        s += __shfl_xor_sync(~0u, s, o);
        q += __shfl_xor_sync(~0u, q, o);
    }
    float mu = s * (1.f / 64.f);
    float var = q * (1.f / 64.f) - mu * mu;
    float rstd = rsqrtf(var + 1e-5f);
    float f0 = (v.x - mu) * rstd * lng[2 * lane] + lnb[2 * lane];
    float f1 = (v.y - mu) * rstd * lng[2 * lane + 1] + lnb[2 * lane + 1];
    ((float2*)g_feat)[n * 32 + lane] = make_float2(f0, f1);
    if (tid < CC) cs[tid] = 0.f;
    __syncthreads();
    atomicAdd(&cs[2 * lane], f0);
    atomicAdd(&cs[2 * lane + 1], f1);
    __syncthreads();
    if (tid < CC) atomicAdd(&g_gsum[tid], cs[tid]);
}

// ---------------- tiny global MLP + misc scalars ----------------
__global__ void k_global(const float* __restrict__ fdir,
                         const float* glw1, const float* glb1,
                         const float* glw2, const float* glb2,
                         const float* glw3, const float* glb3,
                         const float* res_scale) {
    __shared__ float a0[CC], a1[CC], a2[CC];
    int t = threadIdx.x;
    if (t < CC) a0[t] = g_gsum[t] * (1.f / (float)NN);
    __syncthreads();
    if (t < CC) {
        float acc = glb1[t];
        for (int k = 0; k < CC; k++) acc += a0[k] * glw1[k * CC + t];
        a1[t] = gelu_exact(acc);
    }
    __syncthreads();
    if (t < CC) {
        float acc = glb2[t];
        for (int k = 0; k < CC; k++) acc += a1[k] * glw2[k * CC + t];
        a2[t] = gelu_exact(acc);
    }
    __syncthreads();
    if (t < CC) {
        float acc = glb3[t];
        for (int k = 0; k < CC; k++) acc += a2[k] * glw3[k * CC + t];
        g_gctx[t] = acc;
    }
    if (t == 0) {
        float u0 = fdir[0], u1 = fdir[1], u2 = fdir[2];
        float inv = 1.f / (sqrtf(u0 * u0 + u1 * u1 + u2 * u2) + 1e-8f);
        g_misc[0] = u0 * inv; g_misc[1] = u1 * inv; g_misc[2] = u2 * inv;
        g_misc[3] = tanhf(res_scale[0]);
    }
}

// ---------------- tiled GEMM: [64 x K](smem) @ [K x NOUT](gmem, staged) -> [64 x NOUT](smem)
// 256 threads, 16x16 grid; thread (tx,ty) computes rows [4ty,4ty+4) and the
// f32x2 column pairs {32p + 2tx}. The {32p+2tx} ownership makes the weight
// LDS.64 reads conflict-free: per half-warp the 16 addresses are one
// contiguous 128B block (banks 0..31 exactly once), broadcast to the other
// half-warp.
template <int NOUT, bool DOGELU>
__device__ __forceinline__ void tile_gemm(const float* __restrict__ A, int sA, int K,
                                          const float* __restrict__ W,
                                          const float* __restrict__ bias,
                                          float* __restrict__ Ws,
                                          float* __restrict__ Out, int sO, int tid) {
    constexpr int PAIRS = NOUT / 32;     // 4 for NOUT=128, 2 for NOUT=64
    const int tx = tid & 15, ty = tid >> 4;
    const int cb = 2 * tx;               // column base within each 32-wide group
    ull acc[4][PAIRS];
#pragma unroll
    for (int r = 0; r < 4; r++)
#pragma unroll
        for (int p = 0; p < PAIRS; p++) acc[r][p] = 0ULL;

    const float* Ar0 = A + (ty * 4) * sA;

    for (int k0 = 0; k0 < K; k0 += 32) {
        int kc = K - k0; if (kc > 32) kc = 32;
        __syncthreads();
        {
            const float4* src = (const float4*)(W + k0 * NOUT);
            float4* dst = (float4*)Ws;
            int tot = kc * (NOUT / 4);
            for (int i = tid; i < tot; i += 256) dst[i] = src[i];
        }
        __syncthreads();
        if (kc == 32) {
#pragma unroll
            for (int kq = 0; kq < 8; kq++) {
                float4 av[4];
#pragma unroll
                for (int r = 0; r < 4; r++)
                    av[r] = *(const float4*)(Ar0 + r * sA + k0 + kq * 4);
#pragma unroll
                for (int j = 0; j < 4; j++) {
                    const float* wr = Ws + (kq * 4 + j) * NOUT + cb;
                    ull bp[PAIRS];
#pragma unroll
                    for (int p = 0; p < PAIRS; p++)
                        bp[p] = *(const ull*)(wr + 32 * p);
#pragma unroll
                    for (int r = 0; r < 4; r++) {
                        float a = ((const float*)&av[r])[j];
                        ull aa = pack2(a, a);
#pragma unroll
                        for (int p = 0; p < PAIRS; p++) fma2(acc[r][p], aa, bp[p]);
                    }
                }
            }
        } else {
            for (int kk = 0; kk < kc; kk++) {
                const float* wr = Ws + kk * NOUT + cb;
                ull bp[PAIRS];
#pragma unroll
                for (int p = 0; p < PAIRS; p++)
                    bp[p] = *(const ull*)(wr + 32 * p);
#pragma unroll
                for (int r = 0; r < 4; r++) {
                    float a = Ar0[r * sA + k0 + kk];
                    ull aa = pack2(a, a);
#pragma unroll
                    for (int p = 0; p < PAIRS; p++) fma2(acc[r][p], aa, bp[p]);
                }
            }
        }
    }
    // epilogue: write value for logical column 32p+cb (+0/+1)
#pragma unroll
    for (int r = 0; r < 4; r++) {
        float* orow = Out + (ty * 4 + r) * sO;
#pragma unroll
        for (int p = 0; p < PAIRS; p++) {
            int col = 32 * p + cb;
            float2 v = unpack2(acc[r][p]);
            float x0 = v.x + bias[col];
            float x1 = v.y + bias[col + 1];
            if (DOGELU) { x0 = gelu_exact(x0); x1 = gelu_exact(x1); }
            orow[col] = x0;
            orow[col + 1] = x1;
        }
    }
}

// ---------------- edge kernel: gather -> edge MLP -> gate -> atomic scatter ----------------
// dyn smem floats: Xs[64*200) | B1[64*132) | Ws[32*128) | gate[64) | uu[4) | rs[64] cs[64]
#define SME_XS 0
#define SME_B1 12800
#define SME_WS 21248
#define SME_GATE 25344
#define SME_UU 25408
#define SME_IDX 25412
#define SME_EDGE_FLOATS 25540

__global__ void __launch_bounds__(256, 2) k_edge(
    const int* __restrict__ ei, const float* __restrict__ coords,
    const float* ew1, const float* eb1, const float* ew2, const float* eb2,
    const float* ew3, const float* eb3, const float* gw1, const float* gb1,
    const float* gw2, const float* gb2) {
    extern __shared__ float sm[];
    float* Xs = sm + SME_XS;
    float* B1 = sm + SME_B1;
    float* Ws = sm + SME_WS;
    float* gate = sm + SME_GATE;
    float* uu = sm + SME_UU;
    int* rs = (int*)(sm + SME_IDX);
    int* cs2 = rs + 64;
    int tid = threadIdx.x;
    int e0 = blockIdx.x * 64;

    if (tid < 64) { rs[tid] = ei[e0 + tid]; cs2[tid] = ei[EE + e0 + tid]; }
    if (tid < 4) uu[tid] = g_misc[tid];
    __syncthreads();

    for (int idx = tid; idx < 64 * 64; idx += 256) {
        int e = idx >> 6, c = idx & 63;
        float fi = g_feat[rs[e] * 64 + c];
        float fj = g_feat[cs2[e] * 64 + c];
        float* xr = Xs + e * 200;
        xr[c] = fi; xr[64 + c] = fj; xr[128 + c] = fi - fj;
    }
    if (tid < 64) {
        int e = tid, r = rs[e], c = cs2[e];
        float xi0 = coords[r * 3], xi1 = coords[r * 3 + 1], xi2 = coords[r * 3 + 2];
        float xj0 = coords[c * 3], xj1 = coords[c * 3 + 1], xj2 = coords[c * 3 + 2];
        float r0 = xi0 - xj0, r1 = xi1 - xj1, r2 = xi2 - xj2;
        float u0 = uu[0], u1 = uu[1], u2 = uu[2];
        float* xr = Xs + e * 200;
        xr[192] = r0 * r0 + r1 * r1 + r2 * r2;
        xr[193] = xi0 * u0 + xi1 * u1 + xi2 * u2;
        xr[194] = xj0 * u0 + xj1 * u1 + xj2 * u2;
        xr[195] = r0 * u0 + r1 * u1 + r2 * u2;
    }
    __syncthreads();

    tile_gemm<128, true >(Xs, 200, 196, ew1, eb1, Ws, B1, 132, tid);  // h1
    tile_gemm<128, true >(B1, 132, 128, ew2, eb2, Ws, Xs, 132, tid);  // h2
    tile_gemm<128, false>(Xs, 132, 128, ew3, eb3, Ws, B1, 132, tid);  // edge_hidden
    tile_gemm<128, true >(B1, 132, 128, gw1, gb1, Ws, Xs, 132, tid);  // gate hidden
    __syncthreads();

    // gate: 4 threads per edge, interleaved k = 4k'+q for conflict-free LDS
    {
        int e = tid >> 2, q = tid & 3;
        const float* gr = Xs + e * 132;
        float acc = 0.f;
#pragma unroll
        for (int kk = 0; kk < 32; kk++) {
            int k = kk * 4 + q;
            acc += gr[k] * gw2[k];
        }
        acc += __shfl_xor_sync(~0u, acc, 1);
        acc += __shfl_xor_sync(~0u, acc, 2);
        if (q == 0) gate[e] = 1.f / (1.f + expf(-(acc + gb2[0])));
    }
    __syncthreads();

    for (int idx = tid; idx < 64 * 128; idx += 256) {
        int e = idx >> 7, c2 = idx & 127;
        float v = gate[e] * B1[e * 132 + c2];
        atomicAdd(&g_agg[rs[e] * 128 + c2], v);
    }
    if (tid < 64) atomicAdd(&g_deg[rs[tid]], 1.f);
}

// ---------------- node update kernel ----------------
// dyn smem floats: Un[64*260) | B1[64*132) | Ws[32*128) | dg[64)
#define SMU_UN 0
#define SMU_B1 16640
#define SMU_WS 25088
#define SMU_DG 29184
#define SMU_UPD_FLOATS 29248

__global__ void __launch_bounds__(256, 1) k_update(
    const float* uw1, const float* ub1, const float* uw2, const float* ub2,
    const float* uw3, const float* ub3, float* __restrict__ out) {
    extern __shared__ float sm[];
    float* Un = sm + SMU_UN;
    float* B1 = sm + SMU_B1;
    float* Ws = sm + SMU_WS;
    float* dg = sm + SMU_DG;
    int tid = threadIdx.x;
    int n0 = blockIdx.x * 64;

    if (tid < 64) {
        int n = n0 + tid; if (n >= NN) n = NN - 1;
        float d = g_deg[n]; if (d < 1.f) d = 1.f;
        dg[tid] = 1.f / d;
    }
    __syncthreads();
    for (int idx = tid; idx < 64 * 64; idx += 256) {
        int e = idx >> 6, c = idx & 63;
        int n = n0 + e; if (n >= NN) n = NN - 1;
        Un[e * 260 + c] = g_feat[n * 64 + c];
        Un[e * 260 + 192 + c] = g_gctx[c];
    }
    for (int idx = tid; idx < 64 * 128; idx += 256) {
        int e = idx >> 7, c = idx & 127;
        int n = n0 + e; if (n >= NN) n = NN - 1;
        Un[e * 260 + 64 + c] = g_agg[n * 128 + c] * dg[e];
    }
    __syncthreads();

    tile_gemm<128, true >(Un, 260, 256, uw1, ub1, Ws, B1, 132, tid);
    tile_gemm<128, true >(B1, 132, 128, uw2, ub2, Ws, Un, 132, tid);
    tile_gemm<64, false>(Un, 132, 128, uw3, ub3, Ws, B1, 132, tid);
    __syncthreads();

    float ts = g_misc[3];
    for (int idx = tid; idx < 64 * 64; idx += 256) {
        int e = idx >> 6, c = idx & 63;
        int n = n0 + e;
        if (n < NN) out[n * 64 + c] = ts * B1[e * 132 + c];
    }
}

// ---------------- launch ----------------
extern "C" void kernel_launch(void* const* d_in, const int* in_sizes, int n_in,
                              void* d_out, int out_size) {
    const float* coords   = (const float*)d_in[0];
    const float* h        = (const float*)d_in[1];
    const float* fdir     = (const float*)d_in[2];
    const int*   ei       = (const int*)d_in[3];
    const float* ln_g     = (const float*)d_in[4];
    const float* ln_b     = (const float*)d_in[5];
    const float* ew1      = (const float*)d_in[6];
    const float* eb1      = (const float*)d_in[7];
    const float* ew2      = (const float*)d_in[8];
    const float* eb2      = (const float*)d_in[9];
    const float* ew3      = (const float*)d_in[10];
    const float* eb3      = (const float*)d_in[11];
    const float* gw1      = (const float*)d_in[12];
    const float* gb1      = (const float*)d_in[13];
    const float* gw2      = (const float*)d_in[14];
    const float* gb2      = (const float*)d_in[15];
    const float* glw1     = (const float*)d_in[16];
    const float* glb1     = (const float*)d_in[17];
    const float* glw2     = (const float*)d_in[18];
    const float* glb2     = (const float*)d_in[19];
    const float* glw3     = (const float*)d_in[20];
    const float* glb3     = (const float*)d_in[21];
    const float* uw1      = (const float*)d_in[22];
    const float* ub1      = (const float*)d_in[23];
    const float* uw2      = (const float*)d_in[24];
    const float* ub2      = (const float*)d_in[25];
    const float* uw3      = (const float*)d_in[26];
    const float* ub3      = (const float*)d_in[27];
    const float* rscale   = (const float*)d_in[28];
    float* out = (float*)d_out;

    cudaFuncSetAttribute(k_edge, cudaFuncAttributeMaxDynamicSharedMemorySize,
                         SME_EDGE_FLOATS * 4);
    cudaFuncSetAttribute(k_update, cudaFuncAttributeMaxDynamicSharedMemorySize,
                         SMU_UPD_FLOATS * 4);

    k_zero<<<2048, 256>>>();
    k_lnorm<<<NN / 4, 128>>>(h, ln_g, ln_b);
    k_global<<<1, 64>>>(fdir, glw1, glb1, glw2, glb2, glw3, glb3, rscale);
    k_edge<<<EE / 64, 256, SME_EDGE_FLOATS * 4>>>(ei, coords,
        ew1, eb1, ew2, eb2, ew3, eb3, gw1, gb1, gw2, gb2);
    k_update<<<(NN + 63) / 64, 256, SMU_UPD_FLOATS * 4>>>(
        uw1, ub1, uw2, ub2, uw3, ub3, out);
}

// round 3
// speedup vs baseline: 1.9743x; 1.3517x over previous
#include <cuda_runtime.h>

#define NN 50000
#define EE 800000
#define CC 64
#define MCC 128
#define NPAD 50048   // 782*64, padded row count for P/Q

typedef unsigned long long ull;

// ---------------- device scratch ----------------
__device__ __align__(16) float g_feat[NN * CC];
__device__ __align__(16) float g_agg[NN * MCC];
__device__ __align__(16) float g_deg[NN];
__device__ __align__(16) float g_gsum[CC];
__device__ __align__(16) float g_gctx[CC];
__device__ __align__(16) float g_misc[4];          // u0,u1,u2, tanh(res_scale)
__device__ __align__(16) float g_W1a[CC * MCC];    // ew1[0:64]+ew1[128:192]
__device__ __align__(16) float g_W1b[CC * MCC];    // ew1[64:128]-ew1[128:192]
__device__ __align__(16) float g_P[NPAD * MCC];    // feat @ W1a
__device__ __align__(16) float g_Q[NPAD * MCC];    // feat @ W1b
__device__ __align__(16) float g_ub1eff[MCC];      // ub1 + gctx @ uw1[192:256]
__device__ __align__(16) float g_zeros[MCC];       // zero bias

// ---------------- f32x2 packed math ----------------
__device__ __forceinline__ ull pack2(float lo, float hi) {
    ull r; asm("mov.b64 %0, {%1, %2};" : "=l"(r) : "f"(lo), "f"(hi)); return r;
}
__device__ __forceinline__ void fma2(ull& d, ull a, ull b) {
    asm("fma.rn.f32x2 %0, %1, %2, %0;" : "+l"(d) : "l"(a), "l"(b));
}
__device__ __forceinline__ float2 unpack2(ull v) {
    float2 f; asm("mov.b64 {%0, %1}, %2;" : "=f"(f.x), "=f"(f.y) : "l"(v)); return f;
}
__device__ __forceinline__ float gelu_exact(float x) {
    return 0.5f * x * (1.0f + erff(x * 0.7071067811865476f));
}

// ---------------- zero scratch ----------------
__global__ void k_zero() {
    int i = blockIdx.x * blockDim.x + threadIdx.x;
    int stride = gridDim.x * blockDim.x;
    float4 z = make_float4(0.f, 0.f, 0.f, 0.f);
    for (int j = i; j < NN * MCC / 4; j += stride) ((float4*)g_agg)[j] = z;
    for (int j = i; j < NN; j += stride) g_deg[j] = 0.f;
    if (i < CC) g_gsum[i] = 0.f;
    if (i < MCC) g_zeros[i] = 0.f;
}

// ---------------- weight prep: combine ew1 blocks ----------------
__global__ void k_prep(const float* __restrict__ ew1) {
    int i = blockIdx.x * blockDim.x + threadIdx.x;
    int stride = gridDim.x * blockDim.x;
    for (int j = i; j < CC * MCC; j += stride) {
        float wc = ew1[2 * CC * MCC + j];
        g_W1a[j] = ew1[j] + wc;
        g_W1b[j] = ew1[CC * MCC + j] - wc;
    }
}

// ---------------- layernorm + global column-sum partials ----------------
__global__ void k_lnorm(const float* __restrict__ h,
                        const float* __restrict__ lng,
                        const float* __restrict__ lnb) {
    __shared__ float cs[CC];
    int tid = threadIdx.x, lane = tid & 31, w = tid >> 5;
    int n = blockIdx.x * 4 + w;
    float2 v = ((const float2*)h)[n * 32 + lane];
    float s = v.x + v.y, q = v.x * v.x + v.y * v.y;
#pragma unroll
    for (int o = 16; o; o >>= 1) {
        s += __shfl_xor_sync(~0u, s, o);
        q += __shfl_xor_sync(~0u, q, o);
    }
    float mu = s * (1.f / 64.f);
    float var = q * (1.f / 64.f) - mu * mu;
    float rstd = rsqrtf(var + 1e-5f);
    float f0 = (v.x - mu) * rstd * lng[2 * lane] + lnb[2 * lane];
    float f1 = (v.y - mu) * rstd * lng[2 * lane + 1] + lnb[2 * lane + 1];
    ((float2*)g_feat)[n * 32 + lane] = make_float2(f0, f1);
    if (tid < CC) cs[tid] = 0.f;
    __syncthreads();
    atomicAdd(&cs[2 * lane], f0);
    atomicAdd(&cs[2 * lane + 1], f1);
    __syncthreads();
    if (tid < CC) atomicAdd(&g_gsum[tid], cs[tid]);
}

// ---------------- tiny global MLP + misc + effective update bias ----------------
__global__ void k_global(const float* __restrict__ fdir,
                         const float* glw1, const float* glb1,
                         const float* glw2, const float* glb2,
                         const float* glw3, const float* glb3,
                         const float* res_scale,
                         const float* ub1, const float* uw1) {
    __shared__ float a0[CC], a1[CC], a2[CC];
    int t = threadIdx.x;
    if (t < CC) a0[t] = g_gsum[t] * (1.f / (float)NN);
    __syncthreads();
    if (t < CC) {
        float acc = glb1[t];
        for (int k = 0; k < CC; k++) acc += a0[k] * glw1[k * CC + t];
        a1[t] = gelu_exact(acc);
    }
    __syncthreads();
    if (t < CC) {
        float acc = glb2[t];
        for (int k = 0; k < CC; k++) acc += a1[k] * glw2[k * CC + t];
        a2[t] = gelu_exact(acc);
    }
    __syncthreads();
    if (t < CC) {
        float acc = glb3[t];
        for (int k = 0; k < CC; k++) acc += a2[k] * glw3[k * CC + t];
        g_gctx[t] = acc;
        a0[t] = acc;        // reuse a0 as ctx
    }
    __syncthreads();
    // g_ub1eff[c] = ub1[c] + sum_k ctx[k] * uw1[(192+k)*128 + c]
    for (int c = t; c < MCC; c += CC) {
        float acc = ub1[c];
        for (int k = 0; k < CC; k++) acc += a0[k] * uw1[(192 + k) * MCC + c];
        g_ub1eff[c] = acc;
    }
    if (t == 0) {
        float u0 = fdir[0], u1 = fdir[1], u2 = fdir[2];
        float inv = 1.f / (sqrtf(u0 * u0 + u1 * u1 + u2 * u2) + 1e-8f);
        g_misc[0] = u0 * inv; g_misc[1] = u1 * inv; g_misc[2] = u2 * inv;
        g_misc[3] = tanhf(res_scale[0]);
    }
}

// ---------------- tiled GEMM: [64 x K](smem) @ [K x NOUT](gmem, staged) ----------------
// 256 threads; thread (tx,ty) computes rows [4ty,4ty+4) and col groups {64g+4tx}.
// B loads are LDS.128 (ulonglong2), conflict-free: half-warp covers one
// contiguous 256B block. Out may be shared or global (sO stride, %4==0).
template <int NOUT, bool DOGELU>
__device__ __forceinline__ void tile_gemm(const float* __restrict__ A, int sA, int K,
                                          const float* __restrict__ W,
                                          const float* __restrict__ bias,
                                          float* __restrict__ Ws,
                                          float* __restrict__ Out, int sO, int tid) {
    constexpr int GROUPS = NOUT / 64;    // 2 for 128, 1 for 64
    const int tx = tid & 15, ty = tid >> 4;
    ull acc[4][GROUPS][2];
#pragma unroll
    for (int r = 0; r < 4; r++)
#pragma unroll
        for (int g = 0; g < GROUPS; g++) { acc[r][g][0] = 0ULL; acc[r][g][1] = 0ULL; }

    const float* Ar0 = A + (ty * 4) * sA;

    for (int k0 = 0; k0 < K; k0 += 32) {
        int kc = K - k0; if (kc > 32) kc = 32;
        __syncthreads();
        {
            const float4* src = (const float4*)(W + k0 * NOUT);
            float4* dst = (float4*)Ws;
            int tot = kc * (NOUT / 4);
            for (int i = tid; i < tot; i += 256) dst[i] = src[i];
        }
        __syncthreads();
#pragma unroll
        for (int kq = 0; kq < 8; kq++) {
            if (kq * 4 >= kc) break;
            float4 av[4];
#pragma unroll
            for (int r = 0; r < 4; r++)
                av[r] = *(const float4*)(Ar0 + r * sA + k0 + kq * 4);
#pragma unroll
            for (int j = 0; j < 4; j++) {
                const float* wr = Ws + (kq * 4 + j) * NOUT + 4 * tx;
                ulonglong2 bq[GROUPS];
#pragma unroll
                for (int g = 0; g < GROUPS; g++)
                    bq[g] = *(const ulonglong2*)(wr + 64 * g);
#pragma unroll
                for (int r = 0; r < 4; r++) {
                    float a = ((const float*)&av[r])[j];
                    ull aa = pack2(a, a);
#pragma unroll
                    for (int g = 0; g < GROUPS; g++) {
                        fma2(acc[r][g][0], aa, bq[g].x);
                        fma2(acc[r][g][1], aa, bq[g].y);
                    }
                }
            }
        }
    }
#pragma unroll
    for (int r = 0; r < 4; r++) {
        float* orow = Out + (ty * 4 + r) * sO;
#pragma unroll
        for (int g = 0; g < GROUPS; g++) {
            int col = 64 * g + 4 * tx;
            float2 v0 = unpack2(acc[r][g][0]);
            float2 v1 = unpack2(acc[r][g][1]);
            float4 o;
            o.x = v0.x + bias[col];
            o.y = v0.y + bias[col + 1];
            o.z = v1.x + bias[col + 2];
            o.w = v1.y + bias[col + 3];
            if (DOGELU) {
                o.x = gelu_exact(o.x); o.y = gelu_exact(o.y);
                o.z = gelu_exact(o.z); o.w = gelu_exact(o.w);
            }
            *(float4*)(orow + col) = o;
        }
    }
}

// ---------------- node-level P/Q GEMMs: P = feat@W1a, Q = feat@W1b ----------------
// smem: At[64*68] | Ws[32*128]
__global__ void __launch_bounds__(256, 2) k_pq() {
    __shared__ float At[64 * 68];
    __shared__ float Ws[32 * 128];
    int tid = threadIdx.x;
    int n0 = blockIdx.x * 64;
    for (int idx = tid; idx < 64 * 64; idx += 256) {
        int e = idx >> 6, c = idx & 63;
        int n = n0 + e; if (n >= NN) n = NN - 1;
        At[e * 68 + c] = g_feat[n * 64 + c];
    }
    tile_gemm<128, false>(At, 68, 64, g_W1a, g_zeros, Ws, g_P + n0 * MCC, MCC, tid);
    tile_gemm<128, false>(At, 68, 64, g_W1b, g_zeros, Ws, g_Q + n0 * MCC, MCC, tid);
}

// ---------------- edge kernel ----------------
// dyn smem floats:
#define SME_BUFA 0                    // 64*132
#define SME_BUFB 8448                 // 64*132
#define SME_WS   16896                // 32*128
#define SME_WD   20992                // 4*128
#define SME_EB1  21504                // 128
#define SME_GEO  21632                // 64*4
#define SME_GATE 21888                // 64
#define SME_IDX  21952                // 128 ints
#define SME_EDGE_FLOATS 22080

__global__ void __launch_bounds__(256, 2) k_edge(
    const int* __restrict__ ei, const float* __restrict__ coords,
    const float* ew1, const float* eb1,
    const float* ew2, const float* eb2,
    const float* ew3, const float* eb3,
    const float* gw1, const float* gb1,
    const float* gw2, const float* gb2) {
    extern __shared__ float sm[];
    float* bufA = sm + SME_BUFA;
    float* bufB = sm + SME_BUFB;
    float* Ws   = sm + SME_WS;
    float* Wd   = sm + SME_WD;
    float* eb1s = sm + SME_EB1;
    float* geo  = sm + SME_GEO;
    float* gate = sm + SME_GATE;
    int* rs  = (int*)(sm + SME_IDX);
    int* cs2 = rs + 64;
    int tid = threadIdx.x;
    int e0 = blockIdx.x * 64;

    if (tid < 64) { rs[tid] = ei[e0 + tid]; cs2[tid] = ei[EE + e0 + tid]; }
    // Wd = ew1 rows 192..195; eb1 into smem
    for (int i = tid; i < 4 * MCC; i += 256) Wd[i] = ew1[192 * MCC + i];
    if (tid >= 128 && tid < 256) eb1s[tid - 128] = eb1[tid - 128];
    __syncthreads();

    // geo features per edge
    if (tid < 64) {
        int e = tid, r = rs[e], c = cs2[e];
        float xi0 = coords[r * 3], xi1 = coords[r * 3 + 1], xi2 = coords[r * 3 + 2];
        float xj0 = coords[c * 3], xj1 = coords[c * 3 + 1], xj2 = coords[c * 3 + 2];
        float r0 = xi0 - xj0, r1 = xi1 - xj1, r2 = xi2 - xj2;
        float u0 = g_misc[0], u1 = g_misc[1], u2 = g_misc[2];
        geo[e * 4 + 0] = r0 * r0 + r1 * r1 + r2 * r2;
        geo[e * 4 + 1] = xi0 * u0 + xi1 * u1 + xi2 * u2;
        geo[e * 4 + 2] = xj0 * u0 + xj1 * u1 + xj2 * u2;
        geo[e * 4 + 3] = r0 * u0 + r1 * u1 + r2 * u2;
    }
    __syncthreads();

    // build H1 = gelu(P[row] + Q[col] + geo@Wd + eb1) into bufA
    for (int idx = tid; idx < 64 * 32; idx += 256) {
        int e = idx >> 5;
        int c = (idx & 31) * 4;
        const float4 p = *(const float4*)(g_P + rs[e] * MCC + c);
        const float4 q = *(const float4*)(g_Q + cs2[e] * MCC + c);
        float g0 = geo[e * 4], g1 = geo[e * 4 + 1], g2 = geo[e * 4 + 2], g3 = geo[e * 4 + 3];
        float4 w0 = *(const float4*)(Wd + c);
        float4 w1 = *(const float4*)(Wd + MCC + c);
        float4 w2 = *(const float4*)(Wd + 2 * MCC + c);
        float4 w3 = *(const float4*)(Wd + 3 * MCC + c);
        float4 b = *(const float4*)(eb1s + c);
        float4 o;
        o.x = gelu_exact(p.x + q.x + g0 * w0.x + g1 * w1.x + g2 * w2.x + g3 * w3.x + b.x);
        o.y = gelu_exact(p.y + q.y + g0 * w0.y + g1 * w1.y + g2 * w2.y + g3 * w3.y + b.y);
        o.z = gelu_exact(p.z + q.z + g0 * w0.z + g1 * w1.z + g2 * w2.z + g3 * w3.z + b.z);
        o.w = gelu_exact(p.w + q.w + g0 * w0.w + g1 * w1.w + g2 * w2.w + g3 * w3.w + b.w);
        *(float4*)(bufA + e * 132 + c) = o;
    }
    __syncthreads();

    tile_gemm<128, true >(bufA, 132, 128, ew2, eb2, Ws, bufB, 132, tid);  // H2
    tile_gemm<128, false>(bufB, 132, 128, ew3, eb3, Ws, bufA, 132, tid);  // edge_hidden
    tile_gemm<128, true >(bufA, 132, 128, gw1, gb1, Ws, bufB, 132, tid);  // gate hidden
    __syncthreads();

    // gate: 4 threads per edge, interleaved k
    {
        int e = tid >> 2, q = tid & 3;
        const float* gr = bufB + e * 132;
        float acc = 0.f;
#pragma unroll
        for (int kk = 0; kk < 32; kk++) {
            int k = kk * 4 + q;
            acc += gr[k] * gw2[k];
        }
        acc += __shfl_xor_sync(~0u, acc, 1);
        acc += __shfl_xor_sync(~0u, acc, 2);
        if (q == 0) gate[e] = 1.f / (1.f + expf(-(acc + gb2[0])));
    }
    __syncthreads();

    for (int idx = tid; idx < 64 * 128; idx += 256) {
        int e = idx >> 7, c2 = idx & 127;
        float v = gate[e] * bufA[e * 132 + c2];
        atomicAdd(&g_agg[rs[e] * 128 + c2], v);
    }
    if (tid < 64) atomicAdd(&g_deg[rs[tid]], 1.f);
}

// ---------------- node update kernel ----------------
// dyn smem floats: Un[64*196) | B1[64*132) | Ws[32*128) | dg[64)
#define SMU_UN 0
#define SMU_B1 12544
#define SMU_WS 20992
#define SMU_DG 25088
#define SMU_UPD_FLOATS 25152

__global__ void __launch_bounds__(256, 1) k_update(
    const float* uw1, const float* uw2, const float* ub2,
    const float* uw3, const float* ub3, float* __restrict__ out) {
    extern __shared__ float sm[];
    float* Un = sm + SMU_UN;
    float* B1 = sm + SMU_B1;
    float* Ws = sm + SMU_WS;
    float* dg = sm + SMU_DG;
    int tid = threadIdx.x;
    int n0 = blockIdx.x * 64;

    if (tid < 64) {
        int n = n0 + tid; if (n >= NN) n = NN - 1;
        float d = g_deg[n]; if (d < 1.f) d = 1.f;
        dg[tid] = 1.f / d;
    }
    __syncthreads();
    for (int idx = tid; idx < 64 * 64; idx += 256) {
        int e = idx >> 6, c = idx & 63;
        int n = n0 + e; if (n >= NN) n = NN - 1;
        Un[e * 196 + c] = g_feat[n * 64 + c];
    }
    for (int idx = tid; idx < 64 * 128; idx += 256) {
        int e = idx >> 7, c = idx & 127;
        int n = n0 + e; if (n >= NN) n = NN - 1;
        Un[e * 196 + 64 + c] = g_agg[n * 128 + c] * dg[e];
    }
    __syncthreads();

    tile_gemm<128, true >(Un, 196, 192, uw1, g_ub1eff, Ws, B1, 132, tid);
    tile_gemm<128, true >(B1, 132, 128, uw2, ub2, Ws, Un, 132, tid);
    tile_gemm<64,  false>(Un, 132, 128, uw3, ub3, Ws, B1, 68, tid);
    __syncthreads();

    float ts = g_misc[3];
    for (int idx = tid; idx < 64 * 64; idx += 256) {
        int e = idx >> 6, c = idx & 63;
        int n = n0 + e;
        if (n < NN) out[n * 64 + c] = ts * B1[e * 68 + c];
    }
}

// ---------------- launch ----------------
extern "C" void kernel_launch(void* const* d_in, const int* in_sizes, int n_in,
                              void* d_out, int out_size) {
    const float* coords   = (const float*)d_in[0];
    const float* h        = (const float*)d_in[1];
    const float* fdir     = (const float*)d_in[2];
    const int*   ei       = (const int*)d_in[3];
    const float* ln_g     = (const float*)d_in[4];
    const float* ln_b     = (const float*)d_in[5];
    const float* ew1      = (const float*)d_in[6];
    const float* eb1      = (const float*)d_in[7];
    const float* ew2      = (const float*)d_in[8];
    const float* eb2      = (const float*)d_in[9];
    const float* ew3      = (const float*)d_in[10];
    const float* eb3      = (const float*)d_in[11];
    const float* gw1      = (const float*)d_in[12];
    const float* gb1      = (const float*)d_in[13];
    const float* gw2      = (const float*)d_in[14];
    const float* gb2      = (const float*)d_in[15];
    const float* glw1     = (const float*)d_in[16];
    const float* glb1     = (const float*)d_in[17];
    const float* glw2     = (const float*)d_in[18];
    const float* glb2     = (const float*)d_in[19];
    const float* glw3     = (const float*)d_in[20];
    const float* glb3     = (const float*)d_in[21];
    const float* uw1      = (const float*)d_in[22];
    const float* ub1      = (const float*)d_in[23];
    const float* uw2      = (const float*)d_in[24];
    const float* ub2      = (const float*)d_in[25];
    const float* uw3      = (const float*)d_in[26];
    const float* ub3      = (const float*)d_in[27];
    const float* rscale   = (const float*)d_in[28];
    float* out = (float*)d_out;

    cudaFuncSetAttribute(k_edge, cudaFuncAttributeMaxDynamicSharedMemorySize,
                         SME_EDGE_FLOATS * 4);
    cudaFuncSetAttribute(k_update, cudaFuncAttributeMaxDynamicSharedMemorySize,
                         SMU_UPD_FLOATS * 4);

    k_zero<<<2048, 256>>>();
    k_prep<<<32, 256>>>(ew1);
    k_lnorm<<<NN / 4, 128>>>(h, ln_g, ln_b);
    k_global<<<1, 64>>>(fdir, glw1, glb1, glw2, glb2, glw3, glb3, rscale, ub1, uw1);
    k_pq<<<(NN + 63) / 64, 256>>>();
    k_edge<<<EE / 64, 256, SME_EDGE_FLOATS * 4>>>(ei, coords,
        ew1, eb1, ew2, eb2, ew3, eb3, gw1, gb1, gw2, gb2);
    k_update<<<(NN + 63) / 64, 256, SMU_UPD_FLOATS * 4>>>(
        uw1, uw2, ub2, uw3, ub3, out);
}

// round 5
// speedup vs baseline: 3.7421x; 1.8954x over previous
#include <cuda_runtime.h>
#include <cuda_bf16.h>

#define NN 50000
#define EE 800000
#define CC 64
#define MCC 128
#define NPAD 50048

typedef unsigned long long ull;

// ---------------- device scratch ----------------
__device__ __align__(16) float g_feat[NN * CC];
__device__ __align__(16) float g_agg[NN * MCC];
__device__ __align__(16) float g_deg[NN];
__device__ __align__(16) float g_gsum[CC];
__device__ __align__(16) float g_gctx[CC];
__device__ __align__(16) float g_misc[4];          // u0,u1,u2, tanh(res_scale)
__device__ __align__(16) float g_W1a[CC * MCC];
__device__ __align__(16) float g_W1b[CC * MCC];
__device__ __align__(16) float g_P[NPAD * MCC];
__device__ __align__(16) float g_Q[NPAD * MCC];
__device__ __align__(16) float g_ub1eff[MCC];
__device__ __align__(16) float g_zeros[MCC];
// mma.sync B fragments: [mat][ (s*16 + jg)*32 + lane ] = {bh0, bh1, bl0, bl1}
// mat 0=ew2, 1=ew3, 2=gw1; b-reg0 covers k=2t,2t+1; b-reg1 covers k=2t+8,2t+9; n = jg*8 + (lane>>2)
__device__ __align__(16) uint4 g_wfrag[3][4096];

// ---------------- f32x2 packed math (SIMT GEMMs) ----------------
__device__ __forceinline__ ull pack2(float lo, float hi) {
    ull r; asm("mov.b64 %0, {%1, %2};" : "=l"(r) : "f"(lo), "f"(hi)); return r;
}
__device__ __forceinline__ void fma2(ull& d, ull a, ull b) {
    asm("fma.rn.f32x2 %0, %1, %2, %0;" : "+l"(d) : "l"(a), "l"(b));
}
__device__ __forceinline__ float2 unpack2(ull v) {
    float2 f; asm("mov.b64 {%0, %1}, %2;" : "=f"(f.x), "=f"(f.y) : "l"(v)); return f;
}
__device__ __forceinline__ float gelu_exact(float x) {
    return 0.5f * x * (1.0f + erff(x * 0.7071067811865476f));
}
__device__ __forceinline__ void split2(float a, float b, unsigned& hi, unsigned& lo) {
    __nv_bfloat162 h = __floats2bfloat162_rn(a, b);
    float ra = a - __bfloat162float(h.x);
    float rb = b - __bfloat162float(h.y);
    __nv_bfloat162 l = __floats2bfloat162_rn(ra, rb);
    hi = *(unsigned*)&h;
    lo = *(unsigned*)&l;
}

#define MMA_BF16(c, a0, a1, a2, a3, b0, b1) \
    asm volatile( \
        "mma.sync.aligned.m16n8k16.row.col.f32.bf16.bf16.f32 " \
        "{%0,%1,%2,%3}, {%4,%5,%6,%7}, {%8,%9}, {%0,%1,%2,%3};" \
        : "+f"((c)[0]), "+f"((c)[1]), "+f"((c)[2]), "+f"((c)[3]) \
        : "r"(a0), "r"(a1), "r"(a2), "r"(a3), "r"(b0), "r"(b1))

// ---------------- zero scratch ----------------
__global__ void k_zero() {
    int i = blockIdx.x * blockDim.x + threadIdx.x;
    int stride = gridDim.x * blockDim.x;
    float4 z = make_float4(0.f, 0.f, 0.f, 0.f);
    for (int j = i; j < NN * MCC / 4; j += stride) ((float4*)g_agg)[j] = z;
    for (int j = i; j < NN; j += stride) g_deg[j] = 0.f;
    if (i < CC) g_gsum[i] = 0.f;
    if (i < MCC) g_zeros[i] = 0.f;
}

// ---------------- weight prep ----------------
__global__ void k_prep(const float* __restrict__ ew1) {
    int i = blockIdx.x * blockDim.x + threadIdx.x;
    int stride = gridDim.x * blockDim.x;
    for (int j = i; j < CC * MCC; j += stride) {
        float wc = ew1[2 * CC * MCC + j];
        g_W1a[j] = ew1[j] + wc;
        g_W1b[j] = ew1[CC * MCC + j] - wc;
    }
}

// mma B-fragment pack for ew2, ew3, gw1 (bf16 hi/lo split)
__global__ void k_prep_w(const float* __restrict__ ew2,
                         const float* __restrict__ ew3,
                         const float* __restrict__ gw1) {
    int m = blockIdx.y;
    const float* W = (m == 0) ? ew2 : (m == 1) ? ew3 : gw1;
    int idx = blockIdx.x * blockDim.x + threadIdx.x;
    if (idx >= 4096) return;
    int lane = idx & 31;
    int jg = (idx >> 5) & 15;
    int s = idx >> 9;
    int n = jg * 8 + (lane >> 2);
    int k = s * 16 + (lane & 3) * 2;
    float w00 = W[k * 128 + n],       w01 = W[(k + 1) * 128 + n];
    float w80 = W[(k + 8) * 128 + n], w81 = W[(k + 9) * 128 + n];
    unsigned h0, l0, h8, l8;
    split2(w00, w01, h0, l0);
    split2(w80, w81, h8, l8);
    g_wfrag[m][idx] = make_uint4(h0, h8, l0, l8);
}

// ---------------- layernorm + global column-sum partials ----------------
__global__ void k_lnorm(const float* __restrict__ h,
                        const float* __restrict__ lng,
                        const float* __restrict__ lnb) {
    __shared__ float cs[CC];
    int tid = threadIdx.x, lane = tid & 31, w = tid >> 5;
    int n = blockIdx.x * 4 + w;
    float2 v = ((const float2*)h)[n * 32 + lane];
    float s = v.x + v.y, q = v.x * v.x + v.y * v.y;
#pragma unroll
    for (int o = 16; o; o >>= 1) {
        s += __shfl_xor_sync(~0u, s, o);
        q += __shfl_xor_sync(~0u, q, o);
    }
    float mu = s * (1.f / 64.f);
    float var = q * (1.f / 64.f) - mu * mu;
    float rstd = rsqrtf(var + 1e-5f);
    float f0 = (v.x - mu) * rstd * lng[2 * lane] + lnb[2 * lane];
    float f1 = (v.y - mu) * rstd * lng[2 * lane + 1] + lnb[2 * lane + 1];
    ((float2*)g_feat)[n * 32 + lane] = make_float2(f0, f1);
    if (tid < CC) cs[tid] = 0.f;
    __syncthreads();
    atomicAdd(&cs[2 * lane], f0);
    atomicAdd(&cs[2 * lane + 1], f1);
    __syncthreads();
    if (tid < CC) atomicAdd(&g_gsum[tid], cs[tid]);
}

// ---------------- tiny global MLP + misc + effective update bias ----------------
__global__ void k_global(const float* __restrict__ fdir,
                         const float* glw1, const float* glb1,
                         const float* glw2, const float* glb2,
                         const float* glw3, const float* glb3,
                         const float* res_scale,
                         const float* ub1, const float* uw1) {
    __shared__ float a0[CC], a1[CC], a2[CC];
    int t = threadIdx.x;
    if (t < CC) a0[t] = g_gsum[t] * (1.f / (float)NN);
    __syncthreads();
    if (t < CC) {
        float acc = glb1[t];
        for (int k = 0; k < CC; k++) acc += a0[k] * glw1[k * CC + t];
        a1[t] = gelu_exact(acc);
    }
    __syncthreads();
    if (t < CC) {
        float acc = glb2[t];
        for (int k = 0; k < CC; k++) acc += a1[k] * glw2[k * CC + t];
        a2[t] = gelu_exact(acc);
    }
    __syncthreads();
    if (t < CC) {
        float acc = glb3[t];
        for (int k = 0; k < CC; k++) acc += a2[k] * glw3[k * CC + t];
        g_gctx[t] = acc;
        a0[t] = acc;
    }
    __syncthreads();
    for (int c = t; c < MCC; c += CC) {
        float acc = ub1[c];
        for (int k = 0; k < CC; k++) acc += a0[k] * uw1[(192 + k) * MCC + c];
        g_ub1eff[c] = acc;
    }
    if (t == 0) {
        float u0 = fdir[0], u1 = fdir[1], u2 = fdir[2];
        float inv = 1.f / (sqrtf(u0 * u0 + u1 * u1 + u2 * u2) + 1e-8f);
        g_misc[0] = u0 * inv; g_misc[1] = u1 * inv; g_misc[2] = u2 * inv;
        g_misc[3] = tanhf(res_scale[0]);
    }
}

// ---------------- f32x2 tiled GEMM (k_pq / k_update) ----------------
template <int NOUT, bool DOGELU>
__device__ __forceinline__ void tile_gemm(const float* __restrict__ A, int sA, int K,
                                          const float* __restrict__ W,
                                          const float* __restrict__ bias,
                                          float* __restrict__ Ws,
                                          float* __restrict__ Out, int sO, int tid) {
    constexpr int GROUPS = NOUT / 64;
    const int tx = tid & 15, ty = tid >> 4;
    ull acc[4][GROUPS][2];
#pragma unroll
    for (int r = 0; r < 4; r++)
#pragma unroll
        for (int g = 0; g < GROUPS; g++) { acc[r][g][0] = 0ULL; acc[r][g][1] = 0ULL; }

    const float* Ar0 = A + (ty * 4) * sA;
    for (int k0 = 0; k0 < K; k0 += 32) {
        int kc = K - k0; if (kc > 32) kc = 32;
        __syncthreads();
        {
            const float4* src = (const float4*)(W + k0 * NOUT);
            float4* dst = (float4*)Ws;
            int tot = kc * (NOUT / 4);
            for (int i = tid; i < tot; i += 256) dst[i] = src[i];
        }
        __syncthreads();
#pragma unroll
        for (int kq = 0; kq < 8; kq++) {
            if (kq * 4 >= kc) break;
            float4 av[4];
#pragma unroll
            for (int r = 0; r < 4; r++)
                av[r] = *(const float4*)(Ar0 + r * sA + k0 + kq * 4);
#pragma unroll
            for (int j = 0; j < 4; j++) {
                const float* wr = Ws + (kq * 4 + j) * NOUT + 4 * tx;
                ulonglong2 bq[GROUPS];
#pragma unroll
                for (int g = 0; g < GROUPS; g++)
                    bq[g] = *(const ulonglong2*)(wr + 64 * g);
#pragma unroll
                for (int r = 0; r < 4; r++) {
                    float a = ((const float*)&av[r])[j];
                    ull aa = pack2(a, a);
#pragma unroll
                    for (int g = 0; g < GROUPS; g++) {
                        fma2(acc[r][g][0], aa, bq[g].x);
                        fma2(acc[r][g][1], aa, bq[g].y);
                    }
                }
            }
        }
    }
#pragma unroll
    for (int r = 0; r < 4; r++) {
        float* orow = Out + (ty * 4 + r) * sO;
#pragma unroll
        for (int g = 0; g < GROUPS; g++) {
            int col = 64 * g + 4 * tx;
            float2 v0 = unpack2(acc[r][g][0]);
            float2 v1 = unpack2(acc[r][g][1]);
            float4 o;
            o.x = v0.x + bias[col];
            o.y = v0.y + bias[col + 1];
            o.z = v1.x + bias[col + 2];
            o.w = v1.y + bias[col + 3];
            if (DOGELU) {
                o.x = gelu_exact(o.x); o.y = gelu_exact(o.y);
                o.z = gelu_exact(o.z); o.w = gelu_exact(o.w);
            }
            *(float4*)(orow + col) = o;
        }
    }
}

// ---------------- P/Q node GEMMs ----------------
__global__ void __launch_bounds__(256, 2) k_pq() {
    __shared__ float At[64 * 68];
    __shared__ float Ws[32 * 128];
    int tid = threadIdx.x;
    int n0 = blockIdx.x * 64;
    for (int idx = tid; idx < 64 * 64; idx += 256) {
        int e = idx >> 6, c = idx & 63;
        int n = n0 + e; if (n >= NN) n = NN - 1;
        At[e * 68 + c] = g_feat[n * 64 + c];
    }
    tile_gemm<128, false>(At, 68, 64, g_W1a, g_zeros, Ws, g_P + n0 * MCC, MCC, tid);
    tile_gemm<128, false>(At, 68, 64, g_W1b, g_zeros, Ws, g_Q + n0 * MCC, MCC, tid);
}

// ---------------- edge kernel: mma.sync bf16-split ----------------
// A rows padded to 136 bf16 (272B) -> conflict-free a-frag LDS
#define ASTRIDE 272
#define SB_AH   0
#define SB_AL   17408
#define SB_HB   34816
#define SB_GEO  67584
#define SB_GP   68608
#define SB_GATE 69120
#define SB_EB2  69376
#define SB_EB3  69888
#define SB_GB1  70400
#define SB_GW2  70912
#define SB_EB1  71424
#define SB_WD   71936
#define SB_RS   73984
#define SB_CS   74240
#define SB_EDGE_BYTES 74496

// compute one 64x128 GEMM: acc[8][4] per thread; A = (Ah,Al) in smem; B frags in Wf
__device__ __forceinline__ void mma_pass(const char* sm, const uint4* __restrict__ Wf,
                                         float acc[8][4], int wid, int lane) {
    const int r = wid & 3, ch = wid >> 2;
    const int g = lane >> 2, t = lane & 3;
    const char* Ah = sm + SB_AH;
    const char* Al = sm + SB_AL;
    const int ro0 = (r * 16 + g) * ASTRIDE;
    const int ro1 = ro0 + 8 * ASTRIDE;
#pragma unroll
    for (int s = 0; s < 8; s++) {
        const int cb = s * 32 + 4 * t;
        unsigned ah0 = *(const unsigned*)(Ah + ro0 + cb);
        unsigned ah1 = *(const unsigned*)(Ah + ro1 + cb);
        unsigned ah2 = *(const unsigned*)(Ah + ro0 + cb + 16);
        unsigned ah3 = *(const unsigned*)(Ah + ro1 + cb + 16);
        unsigned al0 = *(const unsigned*)(Al + ro0 + cb);
        unsigned al1 = *(const unsigned*)(Al + ro1 + cb);
        unsigned al2 = *(const unsigned*)(Al + ro0 + cb + 16);
        unsigned al3 = *(const unsigned*)(Al + ro1 + cb + 16);
        const uint4* wp = Wf + (s * 16 + ch * 8) * 32 + lane;
#pragma unroll
        for (int j = 0; j < 8; j++) {
            uint4 w = __ldg(wp + j * 32);
            MMA_BF16(acc[j], ah0, ah1, ah2, ah3, w.x, w.y);
            MMA_BF16(acc[j], ah0, ah1, ah2, ah3, w.z, w.w);
            MMA_BF16(acc[j], al0, al1, al2, al3, w.x, w.y);
        }
    }
}

__global__ void __launch_bounds__(256, 2) k_edge(
    const int* __restrict__ ei, const float* __restrict__ coords,
    const float* __restrict__ ew1, const float* __restrict__ eb1,
    const float* __restrict__ eb2, const float* __restrict__ eb3,
    const float* __restrict__ gb1, const float* __restrict__ gw2,
    const float* __restrict__ gb2) {
    extern __shared__ char sm[];
    char* Ah    = sm + SB_AH;
    char* Al    = sm + SB_AL;
    float* Hbuf = (float*)(sm + SB_HB);
    float* geo  = (float*)(sm + SB_GEO);
    float* gp   = (float*)(sm + SB_GP);
    float* gateS = (float*)(sm + SB_GATE);
    float* eb2s = (float*)(sm + SB_EB2);
    float* eb3s = (float*)(sm + SB_EB3);
    float* gb1s = (float*)(sm + SB_GB1);
    float* gw2s = (float*)(sm + SB_GW2);
    float* eb1s = (float*)(sm + SB_EB1);
    float* Wd   = (float*)(sm + SB_WD);
    int* rs = (int*)(sm + SB_RS);
    int* cs = (int*)(sm + SB_CS);

    const int tid = threadIdx.x;
    const int wid = tid >> 5, lane = tid & 31;
    const int e0 = blockIdx.x * 64;

    if (tid < 64) {
        rs[tid] = ei[e0 + tid];
        cs[tid] = ei[EE + e0 + tid];
    }
    if (tid < 128) {
        eb2s[tid] = eb2[tid];
        eb3s[tid] = eb3[tid];
        gb1s[tid] = gb1[tid];
        gw2s[tid] = gw2[tid];
        eb1s[tid] = eb1[tid];
    }
    for (int i = tid; i < 4 * 128; i += 256) Wd[i] = ew1[192 * 128 + i];
    __syncthreads();

    if (tid < 64) {
        int e = tid, r = rs[e], c = cs[e];
        float xi0 = coords[r * 3], xi1 = coords[r * 3 + 1], xi2 = coords[r * 3 + 2];
        float xj0 = coords[c * 3], xj1 = coords[c * 3 + 1], xj2 = coords[c * 3 + 2];
        float r0 = xi0 - xj0, r1 = xi1 - xj1, r2 = xi2 - xj2;
        float u0 = g_misc[0], u1 = g_misc[1], u2 = g_misc[2];
        geo[e * 4 + 0] = r0 * r0 + r1 * r1 + r2 * r2;
        geo[e * 4 + 1] = xi0 * u0 + xi1 * u1 + xi2 * u2;
        geo[e * 4 + 2] = xj0 * u0 + xj1 * u1 + xj2 * u2;
        geo[e * 4 + 3] = r0 * u0 + r1 * u1 + r2 * u2;
    }
    __syncthreads();

    // ---- build H1 = gelu(P[row] + Q[col] + geo@Wd + eb1) -> Ah/Al ----
    for (int idx = tid; idx < 64 * 16; idx += 256) {
        int e = idx >> 4, c0 = (idx & 15) * 8;
        const float* Pr = g_P + rs[e] * MCC + c0;
        const float* Qr = g_Q + cs[e] * MCC + c0;
        float4 p0 = *(const float4*)Pr, p1 = *(const float4*)(Pr + 4);
        float4 q0 = *(const float4*)Qr, q1 = *(const float4*)(Qr + 4);
        float ge0 = geo[e * 4], ge1 = geo[e * 4 + 1], ge2 = geo[e * 4 + 2], ge3 = geo[e * 4 + 3];
        float h[8];
#pragma unroll
        for (int j = 0; j < 8; j++) {
            int c = c0 + j;
            float pq = (j < 4) ? ((const float*)&p0)[j] + ((const float*)&q0)[j]
                               : ((const float*)&p1)[j - 4] + ((const float*)&q1)[j - 4];
            float v = pq + ge0 * Wd[c] + ge1 * Wd[128 + c] + ge2 * Wd[256 + c]
                    + ge3 * Wd[384 + c] + eb1s[c];
            h[j] = gelu_exact(v);
        }
        unsigned hi[4], lo[4];
#pragma unroll
        for (int j = 0; j < 4; j++) split2(h[2 * j], h[2 * j + 1], hi[j], lo[j]);
        *(uint4*)(Ah + e * ASTRIDE + c0 * 2) = make_uint4(hi[0], hi[1], hi[2], hi[3]);
        *(uint4*)(Al + e * ASTRIDE + c0 * 2) = make_uint4(lo[0], lo[1], lo[2], lo[3]);
    }
    __syncthreads();

    const int r = wid & 3, ch = wid >> 2;
    const int g = lane >> 2, t = lane & 3;
    const int R0 = r * 16 + g, R1 = R0 + 8;

    // ---- GEMM1: H2 = gelu(H1 @ ew2 + eb2) ----
    {
        float acc[8][4];
#pragma unroll
        for (int j = 0; j < 8; j++)
#pragma unroll
            for (int q = 0; q < 4; q++) acc[j][q] = 0.f;
        mma_pass(sm, g_wfrag[0], acc, wid, lane);
        __syncthreads();
#pragma unroll
        for (int j = 0; j < 8; j++) {
            int col = ch * 64 + j * 8 + 2 * t;
            float x0 = gelu_exact(acc[j][0] + eb2s[col]);
            float x1 = gelu_exact(acc[j][1] + eb2s[col + 1]);
            float x2 = gelu_exact(acc[j][2] + eb2s[col]);
            float x3 = gelu_exact(acc[j][3] + eb2s[col + 1]);
            unsigned hi, lo;
            split2(x0, x1, hi, lo);
            *(unsigned*)(Ah + R0 * ASTRIDE + col * 2) = hi;
            *(unsigned*)(Al + R0 * ASTRIDE + col * 2) = lo;
            split2(x2, x3, hi, lo);
            *(unsigned*)(Ah + R1 * ASTRIDE + col * 2) = hi;
            *(unsigned*)(Al + R1 * ASTRIDE + col * 2) = lo;
        }
        __syncthreads();
    }

    // ---- GEMM2: hidden = H2 @ ew3 + eb3 (f32 -> Hbuf, split -> Ah/Al) ----
    {
        float acc[8][4];
#pragma unroll
        for (int j = 0; j < 8; j++)
#pragma unroll
            for (int q = 0; q < 4; q++) acc[j][q] = 0.f;
        mma_pass(sm, g_wfrag[1], acc, wid, lane);
        __syncthreads();
#pragma unroll
        for (int j = 0; j < 8; j++) {
            int col = ch * 64 + j * 8 + 2 * t;
            float x0 = acc[j][0] + eb3s[col];
            float x1 = acc[j][1] + eb3s[col + 1];
            float x2 = acc[j][2] + eb3s[col];
            float x3 = acc[j][3] + eb3s[col + 1];
            *(float2*)(Hbuf + R0 * 128 + col) = make_float2(x0, x1);
            *(float2*)(Hbuf + R1 * 128 + col) = make_float2(x2, x3);
            unsigned hi, lo;
            split2(x0, x1, hi, lo);
            *(unsigned*)(Ah + R0 * ASTRIDE + col * 2) = hi;
            *(unsigned*)(Al + R0 * ASTRIDE + col * 2) = lo;
            split2(x2, x3, hi, lo);
            *(unsigned*)(Ah + R1 * ASTRIDE + col * 2) = hi;
            *(unsigned*)(Al + R1 * ASTRIDE + col * 2) = lo;
        }
        __syncthreads();
    }

    // ---- GEMM3: gate hidden = hidden @ gw1 + gb1 -> gelu -> dot gw2 ----
    {
        float acc[8][4];
#pragma unroll
        for (int j = 0; j < 8; j++)
#pragma unroll
            for (int q = 0; q < 4; q++) acc[j][q] = 0.f;
        mma_pass(sm, g_wfrag[2], acc, wid, lane);
        float p0 = 0.f, p1 = 0.f;
#pragma unroll
        for (int j = 0; j < 8; j++) {
            int col = ch * 64 + j * 8 + 2 * t;
            p0 += gw2s[col] * gelu_exact(acc[j][0] + gb1s[col])
                + gw2s[col + 1] * gelu_exact(acc[j][1] + gb1s[col + 1]);
            p1 += gw2s[col] * gelu_exact(acc[j][2] + gb1s[col])
                + gw2s[col + 1] * gelu_exact(acc[j][3] + gb1s[col + 1]);
        }
        p0 += __shfl_xor_sync(~0u, p0, 1);
        p0 += __shfl_xor_sync(~0u, p0, 2);
        p1 += __shfl_xor_sync(~0u, p1, 1);
        p1 += __shfl_xor_sync(~0u, p1, 2);
        if (t == 0) {
            gp[ch * 64 + R0] = p0;
            gp[ch * 64 + R1] = p1;
        }
        __syncthreads();
        if (tid < 64) {
            float a = gp[tid] + gp[64 + tid] + gb2[0];
            gateS[tid] = 1.f / (1.f + expf(-a));
        }
        __syncthreads();
    }

    // ---- scatter msg = gate * hidden ----
    for (int idx = tid; idx < 64 * 128; idx += 256) {
        int e = idx >> 7, c2 = idx & 127;
        float v = gateS[e] * Hbuf[e * 128 + c2];
        atomicAdd(&g_agg[rs[e] * 128 + c2], v);
    }
    if (tid < 64) atomicAdd(&g_deg[rs[tid]], 1.f);
}

// ---------------- node update kernel ----------------
#define SMU_UN 0
#define SMU_B1 12544
#define SMU_WS 20992
#define SMU_DG 25088
#define SMU_UPD_FLOATS 25152

__global__ void __launch_bounds__(256, 1) k_update(
    const float* uw1, const float* uw2, const float* ub2,
    const float* uw3, const float* ub3, float* __restrict__ out) {
    extern __shared__ float smf[];
    float* Un = smf + SMU_UN;
    float* B1 = smf + SMU_B1;
    float* Ws = smf + SMU_WS;
    float* dg = smf + SMU_DG;
    int tid = threadIdx.x;
    int n0 = blockIdx.x * 64;

    if (tid < 64) {
        int n = n0 + tid; if (n >= NN) n = NN - 1;
        float d = g_deg[n]; if (d < 1.f) d = 1.f;
        dg[tid] = 1.f / d;
    }
    __syncthreads();
    for (int idx = tid; idx < 64 * 64; idx += 256) {
        int e = idx >> 6, c = idx & 63;
        int n = n0 + e; if (n >= NN) n = NN - 1;
        Un[e * 196 + c] = g_feat[n * 64 + c];
    }
    for (int idx = tid; idx < 64 * 128; idx += 256) {
        int e = idx >> 7, c = idx & 127;
        int n = n0 + e; if (n >= NN) n = NN - 1;
        Un[e * 196 + 64 + c] = g_agg[n * 128 + c] * dg[e];
    }
    __syncthreads();

    tile_gemm<128, true >(Un, 196, 192, uw1, g_ub1eff, Ws, B1, 132, tid);
    tile_gemm<128, true >(B1, 132, 128, uw2, ub2, Ws, Un, 132, tid);
    tile_gemm<64,  false>(Un, 132, 128, uw3, ub3, Ws, B1, 68, tid);
    __syncthreads();

    float ts = g_misc[3];
    for (int idx = tid; idx < 64 * 64; idx += 256) {
        int e = idx >> 6, c = idx & 63;
        int n = n0 + e;
        if (n < NN) out[n * 64 + c] = ts * B1[e * 68 + c];
    }
}

// ---------------- launch ----------------
extern "C" void kernel_launch(void* const* d_in, const int* in_sizes, int n_in,
                              void* d_out, int out_size) {
    const float* coords   = (const float*)d_in[0];
    const float* h        = (const float*)d_in[1];
    const float* fdir     = (const float*)d_in[2];
    const int*   ei       = (const int*)d_in[3];
    const float* ln_g     = (const float*)d_in[4];
    const float* ln_b     = (const float*)d_in[5];
    const float* ew1      = (const float*)d_in[6];
    const float* eb1      = (const float*)d_in[7];
    const float* ew2      = (const float*)d_in[8];
    const float* eb2      = (const float*)d_in[9];
    const float* ew3      = (const float*)d_in[10];
    const float* eb3      = (const float*)d_in[11];
    const float* gw1      = (const float*)d_in[12];
    const float* gb1      = (const float*)d_in[13];
    const float* gw2      = (const float*)d_in[14];
    const float* gb2      = (const float*)d_in[15];
    const float* glw1     = (const float*)d_in[16];
    const float* glb1     = (const float*)d_in[17];
    const float* glw2     = (const float*)d_in[18];
    const float* glb2     = (const float*)d_in[19];
    const float* glw3     = (const float*)d_in[20];
    const float* glb3     = (const float*)d_in[21];
    const float* uw1      = (const float*)d_in[22];
    const float* ub1      = (const float*)d_in[23];
    const float* uw2      = (const float*)d_in[24];
    const float* ub2      = (const float*)d_in[25];
    const float* uw3      = (const float*)d_in[26];
    const float* ub3      = (const float*)d_in[27];
    const float* rscale   = (const float*)d_in[28];
    float* out = (float*)d_out;

    cudaFuncSetAttribute(k_edge, cudaFuncAttributeMaxDynamicSharedMemorySize,
                         SB_EDGE_BYTES);
    cudaFuncSetAttribute(k_update, cudaFuncAttributeMaxDynamicSharedMemorySize,
                         SMU_UPD_FLOATS * 4);

    k_zero<<<2048, 256>>>();
    k_prep<<<32, 256>>>(ew1);
    {
        dim3 gdim(16, 3);
        k_prep_w<<<gdim, 256>>>(ew2, ew3, gw1);
    }
    k_lnorm<<<NN / 4, 128>>>(h, ln_g, ln_b);
    k_global<<<1, 64>>>(fdir, glw1, glb1, glw2, glb2, glw3, glb3, rscale, ub1, uw1);
    k_pq<<<(NN + 63) / 64, 256>>>();
    k_edge<<<EE / 64, 256, SB_EDGE_BYTES>>>(ei, coords,
        ew1, eb1, eb2, eb3, gb1, gw2, gb2);
    k_update<<<(NN + 63) / 64, 256, SMU_UPD_FLOATS * 4>>>(
        uw1, uw2, ub2, uw3, ub3, out);
}